// round 3
// baseline (speedup 1.0000x reference)
#include <cuda_runtime.h>
#include <math.h>

#define NS 2048
#define NB 2
#define NH 16
#define NDK 64
#define ND 1024
#define MT (NB*NS)          // 4096 rows total
#define QKV_N (3*ND)        // 3072

// Scratch (allocation-free rule: __device__ globals)
__device__ float g_Q[NB*NH*NS*NDK];   // [b][h][s][d]
__device__ float g_K[NB*NH*NS*NDK];
__device__ float g_V[NB*NH*NS*NDK];
__device__ float g_AO[MT*ND];         // attention output, [b*s][h*dk]

// ---------------------------------------------------------------------------
// Generic 64x64 output tile, K=1024 reduction:  C[m,n] = sum_k A[m,k]*Bt[n,k]
// 256 threads, 4x4 per thread. Smem tiles stored k-major (transposed) so the
// compute loop does conflict-free float4 LDS.
// ---------------------------------------------------------------------------
__device__ __forceinline__ void gemm_tile(const float* __restrict__ A,
                                          const float* __restrict__ Bt,
                                          int m0, int n0, int tid,
                                          float acc[4][4])
{
    __shared__ float As[16][68];   // As[k][m]
    __shared__ float Bs[16][68];   // Bs[k][n]
    const int ty = tid >> 4;       // 0..15 (row group)
    const int tx = tid & 15;       // 0..15 (col group)
    const int lrow = tid >> 2;     // 0..63
    const int lcol = (tid & 3) * 4;// 0,4,8,12

    for (int k0 = 0; k0 < ND; k0 += 16) {
        float4 a = *(const float4*)&A [(size_t)(m0 + lrow) * ND + k0 + lcol];
        float4 b = *(const float4*)&Bt[(size_t)(n0 + lrow) * ND + k0 + lcol];
        As[lcol+0][lrow] = a.x; As[lcol+1][lrow] = a.y;
        As[lcol+2][lrow] = a.z; As[lcol+3][lrow] = a.w;
        Bs[lcol+0][lrow] = b.x; Bs[lcol+1][lrow] = b.y;
        Bs[lcol+2][lrow] = b.z; Bs[lcol+3][lrow] = b.w;
        __syncthreads();
#pragma unroll
        for (int kk = 0; kk < 16; kk++) {
            float4 av = *(const float4*)&As[kk][ty*4];
            float4 bv = *(const float4*)&Bs[kk][tx*4];
            float a4[4] = {av.x, av.y, av.z, av.w};
            float b4[4] = {bv.x, bv.y, bv.z, bv.w};
#pragma unroll
            for (int i = 0; i < 4; i++)
#pragma unroll
                for (int j = 0; j < 4; j++)
                    acc[i][j] = fmaf(a4[i], b4[j], acc[i][j]);
        }
        __syncthreads();
    }
}

// ---------------------------------------------------------------------------
// Stage 1: QKV projection. Scatter-writes into per-head [b][h][s][d] layout.
// grid = (48, 64): x over 3072/64 n-tiles, y over 4096/64 m-tiles.
// ---------------------------------------------------------------------------
__global__ void __launch_bounds__(256)
qkv_kernel(const float* __restrict__ X, const float* __restrict__ Wqkv)
{
    float acc[4][4] = {};
    const int m0 = blockIdx.y * 64;
    const int n0 = blockIdx.x * 64;
    const int tid = threadIdx.x;
    gemm_tile(X, Wqkv, m0, n0, tid, acc);

    const int ty = tid >> 4, tx = tid & 15;
    const int part = n0 / ND;              // 0=Q 1=K 2=V (64 | 1024)
    const int h = (n0 % ND) / NDK;         // head, constant per block
    float* dst = (part == 0) ? g_Q : (part == 1) ? g_K : g_V;
#pragma unroll
    for (int i = 0; i < 4; i++) {
        int m = m0 + ty*4 + i;
        int b = m >> 11;          // / 2048
        int s = m & 2047;
        float4 v = make_float4(acc[i][0], acc[i][1], acc[i][2], acc[i][3]);
        *(float4*)&dst[(((size_t)(b*NH + h))*NS + s)*NDK + tx*4] = v;
    }
}

// ---------------------------------------------------------------------------
// Stage 2: causal flash attention, fp32, BQ=BK=64, 256 threads.
// Q,K smem transposed [d][row]; V natural [k][d]; P padded stride 65.
// grid = (32 qtiles, 32 bh)
// ---------------------------------------------------------------------------
__global__ void __launch_bounds__(256)
attn_kernel()
{
    extern __shared__ float sm[];
    float* Qs    = sm;                  // [64][68]  Qs[d][r], pre-scaled
    float* Ks    = Qs + 64*68;          // [64][68]  Ks[d][c]
    float* Vs    = Ks + 64*68;          // [64][64]  Vs[k][d]
    float* Ps    = Vs + 64*64;          // [64][65]  scores / probs
    float* row_m  = Ps + 64*65;         // [64]
    float* row_l  = row_m + 64;         // [64]
    float* row_sc = row_l + 64;         // [64]

    const int tid = threadIdx.x;
    const int ty = tid >> 4, tx = tid & 15;
    const int qt = blockIdx.x;
    const int bh = blockIdx.y;
    const int q0 = qt * 64;

    const float* Qg = g_Q + (size_t)bh * NS * NDK;
    const float* Kg = g_K + (size_t)bh * NS * NDK;
    const float* Vg = g_V + (size_t)bh * NS * NDK;

    const float scale = 0.125f;   // 1/sqrt(64)
#pragma unroll
    for (int it = 0; it < 4; it++) {
        int idx = it*256 + tid;
        int r = idx >> 4;
        int c = (idx & 15) * 4;
        float4 v = *(const float4*)&Qg[(size_t)(q0 + r)*NDK + c];
        Qs[(c+0)*68 + r] = v.x * scale;
        Qs[(c+1)*68 + r] = v.y * scale;
        Qs[(c+2)*68 + r] = v.z * scale;
        Qs[(c+3)*68 + r] = v.w * scale;
    }
    if (tid < 64) { row_m[tid] = -INFINITY; row_l[tid] = 0.f; }

    float o[4][4] = {};

    for (int kt = 0; kt <= qt; kt++) {
        const int k0 = kt * 64;
        __syncthreads();   // Q/init ready (it 0); protect Ks/Vs/Ps reuse (it>0)
#pragma unroll
        for (int it = 0; it < 4; it++) {
            int idx = it*256 + tid;
            int r = idx >> 4;
            int c = (idx & 15) * 4;
            float4 kv = *(const float4*)&Kg[(size_t)(k0 + r)*NDK + c];
            Ks[(c+0)*68 + r] = kv.x; Ks[(c+1)*68 + r] = kv.y;
            Ks[(c+2)*68 + r] = kv.z; Ks[(c+3)*68 + r] = kv.w;
            float4 vv = *(const float4*)&Vg[(size_t)(k0 + r)*NDK + c];
            *(float4*)&Vs[r*64 + c] = vv;
        }
        __syncthreads();

        // scores S = (Q*scale) . K^T   (4x4 per thread)
        float s[4][4] = {};
#pragma unroll
        for (int dd = 0; dd < 64; dd++) {
            float4 qa = *(const float4*)&Qs[dd*68 + ty*4];
            float4 kb = *(const float4*)&Ks[dd*68 + tx*4];
            float a4[4] = {qa.x, qa.y, qa.z, qa.w};
            float b4[4] = {kb.x, kb.y, kb.z, kb.w};
#pragma unroll
            for (int i = 0; i < 4; i++)
#pragma unroll
                for (int j = 0; j < 4; j++)
                    s[i][j] = fmaf(a4[i], b4[j], s[i][j]);
        }
        if (kt == qt) {   // causal mask on the diagonal tile
#pragma unroll
            for (int i = 0; i < 4; i++)
#pragma unroll
                for (int j = 0; j < 4; j++)
                    if (tx*4 + j > ty*4 + i) s[i][j] = -INFINITY;
        }
#pragma unroll
        for (int i = 0; i < 4; i++)
#pragma unroll
            for (int j = 0; j < 4; j++)
                Ps[(ty*4 + i)*65 + tx*4 + j] = s[i][j];
        __syncthreads();

        // online softmax, one thread per row
        if (tid < 64) {
            const int r = tid;
            float mold = row_m[r];
            float tmax = -INFINITY;
#pragma unroll 8
            for (int j = 0; j < 64; j++) tmax = fmaxf(tmax, Ps[r*65 + j]);
            float nm = fmaxf(mold, tmax);
            float sc = __expf(mold - nm);     // 0 on first tile (mold=-inf)
            float sum = 0.f;
#pragma unroll 8
            for (int j = 0; j < 64; j++) {
                float p = __expf(Ps[r*65 + j] - nm);
                Ps[r*65 + j] = p;
                sum += p;
            }
            row_l[r]  = row_l[r] * sc + sum;
            row_m[r]  = nm;
            row_sc[r] = sc;
        }
        __syncthreads();

        // rescale accumulator, then O += P . V
        float scr[4];
#pragma unroll
        for (int i = 0; i < 4; i++) scr[i] = row_sc[ty*4 + i];
#pragma unroll
        for (int i = 0; i < 4; i++)
#pragma unroll
            for (int j = 0; j < 4; j++) o[i][j] *= scr[i];
#pragma unroll
        for (int j = 0; j < 64; j++) {
            float4 v = *(const float4*)&Vs[j*64 + tx*4];
            float p0 = Ps[(ty*4 + 0)*65 + j];
            float p1 = Ps[(ty*4 + 1)*65 + j];
            float p2 = Ps[(ty*4 + 2)*65 + j];
            float p3 = Ps[(ty*4 + 3)*65 + j];
            o[0][0] = fmaf(p0, v.x, o[0][0]); o[0][1] = fmaf(p0, v.y, o[0][1]);
            o[0][2] = fmaf(p0, v.z, o[0][2]); o[0][3] = fmaf(p0, v.w, o[0][3]);
            o[1][0] = fmaf(p1, v.x, o[1][0]); o[1][1] = fmaf(p1, v.y, o[1][1]);
            o[1][2] = fmaf(p1, v.z, o[1][2]); o[1][3] = fmaf(p1, v.w, o[1][3]);
            o[2][0] = fmaf(p2, v.x, o[2][0]); o[2][1] = fmaf(p2, v.y, o[2][1]);
            o[2][2] = fmaf(p2, v.z, o[2][2]); o[2][3] = fmaf(p2, v.w, o[2][3]);
            o[3][0] = fmaf(p3, v.x, o[3][0]); o[3][1] = fmaf(p3, v.y, o[3][1]);
            o[3][2] = fmaf(p3, v.z, o[3][2]); o[3][3] = fmaf(p3, v.w, o[3][3]);
        }
    }

    // epilogue: O / l, write back to [b*s][h*dk]
    const int b = bh >> 4, h = bh & 15;
#pragma unroll
    for (int i = 0; i < 4; i++) {
        float inv = 1.0f / row_l[ty*4 + i];
        int sN = q0 + ty*4 + i;
        float4 v = make_float4(o[i][0]*inv, o[i][1]*inv, o[i][2]*inv, o[i][3]*inv);
        *(float4*)&g_AO[((size_t)(b*NS + sN))*ND + h*NDK + tx*4] = v;
    }
}

// ---------------------------------------------------------------------------
// Stage 3: output projection.  grid = (16, 64)
// ---------------------------------------------------------------------------
__global__ void __launch_bounds__(256)
outproj_kernel(const float* __restrict__ Wout, float* __restrict__ out)
{
    float acc[4][4] = {};
    const int m0 = blockIdx.y * 64;
    const int n0 = blockIdx.x * 64;
    const int tid = threadIdx.x;
    gemm_tile(g_AO, Wout, m0, n0, tid, acc);

    const int ty = tid >> 4, tx = tid & 15;
#pragma unroll
    for (int i = 0; i < 4; i++) {
        float4 v = make_float4(acc[i][0], acc[i][1], acc[i][2], acc[i][3]);
        *(float4*)&out[(size_t)(m0 + ty*4 + i)*ND + n0 + tx*4] = v;
    }
}

// ---------------------------------------------------------------------------

extern "C" void kernel_launch(void* const* d_in, const int* in_sizes, int n_in,
                              void* d_out, int out_size)
{
    const float* X    = (const float*)d_in[0];   // [2,2048,1024]
    const float* Wqkv = (const float*)d_in[1];   // [3072,1024]
    const float* Wout = (const float*)d_in[2];   // [1024,1024]
    float* out = (float*)d_out;                  // [2,2048,1024]

    const int ATTN_SMEM = (64*68*2 + 64*64 + 64*65 + 3*64) * (int)sizeof(float); // 68608 B
    cudaFuncSetAttribute(attn_kernel, cudaFuncAttributeMaxDynamicSharedMemorySize, ATTN_SMEM);

    qkv_kernel<<<dim3(QKV_N/64, MT/64), 256>>>(X, Wqkv);
    attn_kernel<<<dim3(NS/64, NB*NH), 256, ATTN_SMEM>>>();
    outproj_kernel<<<dim3(ND/64, MT/64), 256>>>(Wout, out);
}

// round 6
// speedup vs baseline: 1.7061x; 1.7061x over previous
#include <cuda_runtime.h>
#include <cuda_bf16.h>
#include <math.h>
#include <stdint.h>

#define NS 2048
#define NB 2
#define NH 16
#define NDK 64
#define ND 1024
#define MT (NB*NS)          // 4096 rows total
#define QKV_N (3*ND)        // 3072

// single dynamic-shared symbol for the whole TU (kernels cast as needed)
extern __shared__ char dynsm[];

// Scratch (allocation-free rule: __device__ globals)
__device__ float g_Q[NB*NH*NS*NDK];   // [b][h][s][d] fp32 (attn input)
__device__ float g_K[NB*NH*NS*NDK];
__device__ float g_V[NB*NH*NS*NDK];
__device__ __nv_bfloat16 g_Xhi[MT*ND];
__device__ __nv_bfloat16 g_Xlo[MT*ND];
__device__ __nv_bfloat16 g_Whi[QKV_N*ND];
__device__ __nv_bfloat16 g_Wlo[QKV_N*ND];
__device__ __nv_bfloat16 g_Ohi[ND*ND];
__device__ __nv_bfloat16 g_Olo[ND*ND];
__device__ __nv_bfloat16 g_AOhi[MT*ND];
__device__ __nv_bfloat16 g_AOlo[MT*ND];

// ---------------------------------------------------------------------------
// helpers (portable PTX only: mma.sync / ldmatrix / cp.async — no tcgen05)
// ---------------------------------------------------------------------------
__device__ __forceinline__ uint32_t smem_u32(const void* p){
    uint32_t a;
    asm("{ .reg .u64 t; cvta.to.shared.u64 t, %1; cvt.u32.u64 %0, t; }" : "=r"(a) : "l"(p));
    return a;
}
__device__ __forceinline__ void cp16(uint32_t saddr, const void* g){
    asm volatile("cp.async.cg.shared.global [%0], [%1], 16;" :: "r"(saddr), "l"(g));
}
__device__ __forceinline__ void cp_commit(){
    asm volatile("cp.async.commit_group;" ::: "memory");
}
__device__ __forceinline__ void ldsm_x4(uint32_t r[4], uint32_t addr){
    asm volatile("ldmatrix.sync.aligned.m8n8.x4.shared.b16 {%0,%1,%2,%3}, [%4];"
                 : "=r"(r[0]), "=r"(r[1]), "=r"(r[2]), "=r"(r[3]) : "r"(addr));
}
__device__ __forceinline__ void mma_bf16(float c[4], const uint32_t a[4],
                                         const uint32_t b0, const uint32_t b1){
    asm volatile(
        "mma.sync.aligned.m16n8k16.row.col.f32.bf16.bf16.f32 "
        "{%0,%1,%2,%3}, {%4,%5,%6,%7}, {%8,%9}, {%0,%1,%2,%3};"
        : "+f"(c[0]), "+f"(c[1]), "+f"(c[2]), "+f"(c[3])
        : "r"(a[0]), "r"(a[1]), "r"(a[2]), "r"(a[3]), "r"(b0), "r"(b1));
}

// ---------------------------------------------------------------------------
// fp32 -> (bf16 hi, bf16 lo) split. which: 0=X, 1=Wqkv, 2=Wout
// ---------------------------------------------------------------------------
__global__ void __launch_bounds__(256)
split_convert(const float* __restrict__ src, int which, int n4)
{
    int i = blockIdx.x * 256 + threadIdx.x;
    if (i >= n4) return;
    __nv_bfloat16 *hi, *lo;
    if (which == 0)      { hi = g_Xhi; lo = g_Xlo; }
    else if (which == 1) { hi = g_Whi; lo = g_Wlo; }
    else                 { hi = g_Ohi; lo = g_Olo; }
    float4 v = ((const float4*)src)[i];
    __nv_bfloat16 h0 = __float2bfloat16(v.x);
    __nv_bfloat16 h1 = __float2bfloat16(v.y);
    __nv_bfloat16 h2 = __float2bfloat16(v.z);
    __nv_bfloat16 h3 = __float2bfloat16(v.w);
    __nv_bfloat16 l0 = __float2bfloat16(v.x - __bfloat162float(h0));
    __nv_bfloat16 l1 = __float2bfloat16(v.y - __bfloat162float(h1));
    __nv_bfloat16 l2 = __float2bfloat16(v.z - __bfloat162float(h2));
    __nv_bfloat16 l3 = __float2bfloat16(v.w - __bfloat162float(h3));
    ((__nv_bfloat162*)hi)[2*i]   = __halves2bfloat162(h0, h1);
    ((__nv_bfloat162*)hi)[2*i+1] = __halves2bfloat162(h2, h3);
    ((__nv_bfloat162*)lo)[2*i]   = __halves2bfloat162(l0, l1);
    ((__nv_bfloat162*)lo)[2*i+1] = __halves2bfloat162(l2, l3);
}

// ---------------------------------------------------------------------------
// Split-bf16 warp-MMA GEMM: C[m,n] = sum_k A[m,k]*B[n,k], K=1024.
// CTA tile 128x128, 8 warps (2x4), warp tile 64x32, K chunk 64, 2-stage
// cp.async pipeline, XOR-swizzled smem rows for conflict-free ldmatrix.
// 3 mma passes (hh, hl, lh) into the same fp32 accumulators.
// mode 1: A=Xhi/lo, B=Wqkv hi/lo -> scatter into g_Q/g_K/g_V (fp32).
// mode 0: A=AO hi/lo, B=Wout hi/lo -> Cout [MT x ND] fp32.
// ---------------------------------------------------------------------------
#define KC 64
#define ARR_BYTES (128*128)             // 128 rows x 64 bf16 = 16KB
#define STAGE_BYTES (4*ARR_BYTES)       // Ahi, Alo, Bhi, Blo = 64KB
#define GEMM_SMEM (2*STAGE_BYTES)       // 128KB (epilogue reuses it)

__global__ void __launch_bounds__(256, 1)
gemm_split_kernel(float* __restrict__ Cout, int mode)
{
    char* sm = dynsm;
    const int tid = threadIdx.x;
    const int wid = tid >> 5, lane = tid & 31;
    const int m0 = blockIdx.y * 128;
    const int n0 = blockIdx.x * 128;

    const __nv_bfloat16 *Ahi, *Alo, *Bhi, *Blo;
    if (mode == 1) { Ahi = g_Xhi;  Alo = g_Xlo;  Bhi = g_Whi; Blo = g_Wlo; }
    else           { Ahi = g_AOhi; Alo = g_AOlo; Bhi = g_Ohi; Blo = g_Olo; }

    const uint32_t smb = smem_u32(sm);

    // warp layout: 2 (m) x 4 (n)
    const int wm0 = (wid >> 2) * 64;
    const int wn0 = (wid & 3) * 32;

    float acc[4][4][4];   // [mt][nt][frag]
#pragma unroll
    for (int a = 0; a < 4; a++)
#pragma unroll
        for (int b = 0; b < 4; b++)
#pragma unroll
            for (int c = 0; c < 4; c++) acc[a][b][c] = 0.f;

    // ---- global -> smem stage loader (cp.async, 16 x 16B per thread) ----
    auto load_stage = [&](int stage, int k0) {
        uint32_t sb = smb + stage * STAGE_BYTES;
        const __nv_bfloat16* srcs[4] = {Ahi, Alo, Bhi, Blo};
#pragma unroll
        for (int arr = 0; arr < 4; arr++) {
            const __nv_bfloat16* src = srcs[arr];
            const int base0 = (arr < 2) ? m0 : n0;
            uint32_t abase = sb + arr * ARR_BYTES;
#pragma unroll
            for (int c = 0; c < 4; c++) {
                int linear = c * 256 + tid;      // 0..1023
                int row = linear >> 3;           // 0..127
                int cb  = linear & 7;            // 16B chunk
                uint32_t sa = abase + row * 128 + ((cb ^ (row & 7)) << 4);
                cp16(sa, src + (size_t)(base0 + row) * ND + k0 + cb * 8);
            }
        }
        cp_commit();
    };

    load_stage(0, 0);

#pragma unroll 1
    for (int i = 0; i < 16; i++) {
        if (i < 15) load_stage((i + 1) & 1, (i + 1) * KC);
        if (i < 15) asm volatile("cp.async.wait_group 1;" ::: "memory");
        else        asm volatile("cp.async.wait_group 0;" ::: "memory");
        __syncthreads();

        uint32_t sb = smb + (i & 1) * STAGE_BYTES;
        uint32_t a_hi_b = sb, a_lo_b = sb + ARR_BYTES;
        uint32_t b_hi_b = sb + 2*ARR_BYTES, b_lo_b = sb + 3*ARR_BYTES;

#pragma unroll
        for (int ks = 0; ks < 4; ks++) {
            // A fragments: per m16 tile, ldmatrix.x4, row = lane&15, kchunk by lane>>4
            uint32_t ah[4][4], al[4][4];
            {
                int row = (lane & 15);
                int kb  = ks * 2 + (lane >> 4);
#pragma unroll
                for (int mt = 0; mt < 4; mt++) {
                    int r = wm0 + mt * 16 + row;
                    uint32_t off = r * 128 + (((uint32_t)(kb ^ (r & 7))) << 4);
                    ldsm_x4(ah[mt], a_hi_b + off);
                    ldsm_x4(al[mt], a_lo_b + off);
                }
            }
            // B fragments: x4 covers 2 n8 tiles x 2 kchunks
            uint32_t bh[4][2], bl[4][2];
            {
                int g = lane >> 3;          // 0..3
                int trow = lane & 7;
#pragma unroll
                for (int p = 0; p < 2; p++) {
                    int nrow = wn0 + (p * 2 + (g >> 1)) * 8 + trow;
                    int kb = ks * 2 + (g & 1);
                    uint32_t off = nrow * 128 + (((uint32_t)(kb ^ (nrow & 7))) << 4);
                    uint32_t r4[4];
                    ldsm_x4(r4, b_hi_b + off);
                    bh[p*2][0] = r4[0]; bh[p*2][1] = r4[1];
                    bh[p*2+1][0] = r4[2]; bh[p*2+1][1] = r4[3];
                    ldsm_x4(r4, b_lo_b + off);
                    bl[p*2][0] = r4[0]; bl[p*2][1] = r4[1];
                    bl[p*2+1][0] = r4[2]; bl[p*2+1][1] = r4[3];
                }
            }
#pragma unroll
            for (int mt = 0; mt < 4; mt++)
#pragma unroll
                for (int nt = 0; nt < 4; nt++) {
                    mma_bf16(acc[mt][nt], ah[mt], bh[nt][0], bh[nt][1]);
                    mma_bf16(acc[mt][nt], ah[mt], bl[nt][0], bl[nt][1]);
                    mma_bf16(acc[mt][nt], al[mt], bh[nt][0], bh[nt][1]);
                }
        }
        __syncthreads();   // stage i consumed; safe to overwrite via next cp.async
    }

    // ---- epilogue: acc -> smem (128x132 f32) -> coalesced/scattered global ----
    float* sf = (float*)sm;
    const int g = lane >> 2, t = lane & 3;
#pragma unroll
    for (int mt = 0; mt < 4; mt++)
#pragma unroll
        for (int nt = 0; nt < 4; nt++) {
            int m = wm0 + mt * 16 + g;
            int n = wn0 + nt * 8 + 2 * t;
            sf[m * 132 + n]       = acc[mt][nt][0];
            sf[m * 132 + n + 1]   = acc[mt][nt][1];
            sf[(m + 8) * 132 + n]     = acc[mt][nt][2];
            sf[(m + 8) * 132 + n + 1] = acc[mt][nt][3];
        }
    __syncthreads();

    const int cgrp = (tid & 7) * 4;   // 0..28
    const int rr0  = tid >> 3;        // 0..31
#pragma unroll 1
    for (int cb = 0; cb < 4; cb++) {
        const int col0 = n0 + cb * 32;
        if (mode == 0) {
#pragma unroll
            for (int it = 0; it < 4; it++) {
                int r = rr0 + it * 32;
                float4 v = *(const float4*)&sf[r * 132 + cb * 32 + cgrp];
                *(float4*)&Cout[(size_t)(m0 + r) * ND + col0 + cgrp] = v;
            }
        } else {
            int part = col0 >> 10;
            int rem  = col0 & 1023;
            int h    = rem >> 6;
            int d0   = (rem & 63) + cgrp;
            float* dst = (part == 0) ? g_Q : (part == 1) ? g_K : g_V;
#pragma unroll
            for (int it = 0; it < 4; it++) {
                int r = rr0 + it * 32;
                int m = m0 + r;
                int b = m >> 11, s = m & 2047;
                float4 v = *(const float4*)&sf[r * 132 + cb * 32 + cgrp];
                *(float4*)&dst[(((size_t)(b * NH + h)) * NS + s) * NDK + d0] = v;
            }
        }
    }
}

// ---------------------------------------------------------------------------
// Stage 2: causal flash attention, fp32, BQ=BK=64, 256 threads (proven
// mainloop; epilogue emits AO as split bf16 hi/lo for the out-proj GEMM).
// ---------------------------------------------------------------------------
__global__ void __launch_bounds__(256)
attn_kernel()
{
    float* sm = (float*)dynsm;
    float* Qs    = sm;                  // [64][68]  Qs[d][r], pre-scaled
    float* Ks    = Qs + 64*68;          // [64][68]  Ks[d][c]
    float* Vs    = Ks + 64*68;          // [64][64]  Vs[k][d]
    float* Ps    = Vs + 64*64;          // [64][65]  scores / probs
    float* row_m  = Ps + 64*65;         // [64]
    float* row_l  = row_m + 64;         // [64]
    float* row_sc = row_l + 64;         // [64]

    const int tid = threadIdx.x;
    const int ty = tid >> 4, tx = tid & 15;
    const int qt = blockIdx.x;
    const int bh = blockIdx.y;
    const int q0 = qt * 64;

    const float* Qg = g_Q + (size_t)bh * NS * NDK;
    const float* Kg = g_K + (size_t)bh * NS * NDK;
    const float* Vg = g_V + (size_t)bh * NS * NDK;

    const float scale = 0.125f;   // 1/sqrt(64)
#pragma unroll
    for (int it = 0; it < 4; it++) {
        int idx = it*256 + tid;
        int r = idx >> 4;
        int c = (idx & 15) * 4;
        float4 v = *(const float4*)&Qg[(size_t)(q0 + r)*NDK + c];
        Qs[(c+0)*68 + r] = v.x * scale;
        Qs[(c+1)*68 + r] = v.y * scale;
        Qs[(c+2)*68 + r] = v.z * scale;
        Qs[(c+3)*68 + r] = v.w * scale;
    }
    if (tid < 64) { row_m[tid] = -INFINITY; row_l[tid] = 0.f; }

    float o[4][4] = {};

    for (int kt = 0; kt <= qt; kt++) {
        const int k0 = kt * 64;
        __syncthreads();
#pragma unroll
        for (int it = 0; it < 4; it++) {
            int idx = it*256 + tid;
            int r = idx >> 4;
            int c = (idx & 15) * 4;
            float4 kv = *(const float4*)&Kg[(size_t)(k0 + r)*NDK + c];
            Ks[(c+0)*68 + r] = kv.x; Ks[(c+1)*68 + r] = kv.y;
            Ks[(c+2)*68 + r] = kv.z; Ks[(c+3)*68 + r] = kv.w;
            float4 vv = *(const float4*)&Vg[(size_t)(k0 + r)*NDK + c];
            *(float4*)&Vs[r*64 + c] = vv;
        }
        __syncthreads();

        float s[4][4] = {};
#pragma unroll
        for (int dd = 0; dd < 64; dd++) {
            float4 qa = *(const float4*)&Qs[dd*68 + ty*4];
            float4 kb = *(const float4*)&Ks[dd*68 + tx*4];
            float a4[4] = {qa.x, qa.y, qa.z, qa.w};
            float b4[4] = {kb.x, kb.y, kb.z, kb.w};
#pragma unroll
            for (int i = 0; i < 4; i++)
#pragma unroll
                for (int j = 0; j < 4; j++)
                    s[i][j] = fmaf(a4[i], b4[j], s[i][j]);
        }
        if (kt == qt) {
#pragma unroll
            for (int i = 0; i < 4; i++)
#pragma unroll
                for (int j = 0; j < 4; j++)
                    if (tx*4 + j > ty*4 + i) s[i][j] = -INFINITY;
        }
#pragma unroll
        for (int i = 0; i < 4; i++)
#pragma unroll
            for (int j = 0; j < 4; j++)
                Ps[(ty*4 + i)*65 + tx*4 + j] = s[i][j];
        __syncthreads();

        if (tid < 64) {
            const int r = tid;
            float mold = row_m[r];
            float tmax = -INFINITY;
#pragma unroll 8
            for (int j = 0; j < 64; j++) tmax = fmaxf(tmax, Ps[r*65 + j]);
            float nm = fmaxf(mold, tmax);
            float sc = __expf(mold - nm);
            float sum = 0.f;
#pragma unroll 8
            for (int j = 0; j < 64; j++) {
                float p = __expf(Ps[r*65 + j] - nm);
                Ps[r*65 + j] = p;
                sum += p;
            }
            row_l[r]  = row_l[r] * sc + sum;
            row_m[r]  = nm;
            row_sc[r] = sc;
        }
        __syncthreads();

        float scr[4];
#pragma unroll
        for (int i = 0; i < 4; i++) scr[i] = row_sc[ty*4 + i];
#pragma unroll
        for (int i = 0; i < 4; i++)
#pragma unroll
            for (int j = 0; j < 4; j++) o[i][j] *= scr[i];
#pragma unroll
        for (int j = 0; j < 64; j++) {
            float4 v = *(const float4*)&Vs[j*64 + tx*4];
            float p0 = Ps[(ty*4 + 0)*65 + j];
            float p1 = Ps[(ty*4 + 1)*65 + j];
            float p2 = Ps[(ty*4 + 2)*65 + j];
            float p3 = Ps[(ty*4 + 3)*65 + j];
            o[0][0] = fmaf(p0, v.x, o[0][0]); o[0][1] = fmaf(p0, v.y, o[0][1]);
            o[0][2] = fmaf(p0, v.z, o[0][2]); o[0][3] = fmaf(p0, v.w, o[0][3]);
            o[1][0] = fmaf(p1, v.x, o[1][0]); o[1][1] = fmaf(p1, v.y, o[1][1]);
            o[1][2] = fmaf(p1, v.z, o[1][2]); o[1][3] = fmaf(p1, v.w, o[1][3]);
            o[2][0] = fmaf(p2, v.x, o[2][0]); o[2][1] = fmaf(p2, v.y, o[2][1]);
            o[2][2] = fmaf(p2, v.z, o[2][2]); o[2][3] = fmaf(p2, v.w, o[2][3]);
            o[3][0] = fmaf(p3, v.x, o[3][0]); o[3][1] = fmaf(p3, v.y, o[3][1]);
            o[3][2] = fmaf(p3, v.z, o[3][2]); o[3][3] = fmaf(p3, v.w, o[3][3]);
        }
    }

    // epilogue: O / l, split into bf16 hi/lo at [b*s][h*dk]
    const int b = bh >> 4, h = bh & 15;
#pragma unroll
    for (int i = 0; i < 4; i++) {
        float inv = 1.0f / row_l[ty*4 + i];
        int sN = q0 + ty*4 + i;
        float4 v = make_float4(o[i][0]*inv, o[i][1]*inv, o[i][2]*inv, o[i][3]*inv);
        size_t base = ((size_t)(b*NS + sN))*ND + h*NDK + tx*4;
        __nv_bfloat16 h0 = __float2bfloat16(v.x);
        __nv_bfloat16 h1 = __float2bfloat16(v.y);
        __nv_bfloat16 h2 = __float2bfloat16(v.z);
        __nv_bfloat16 h3 = __float2bfloat16(v.w);
        __nv_bfloat16 l0 = __float2bfloat16(v.x - __bfloat162float(h0));
        __nv_bfloat16 l1 = __float2bfloat16(v.y - __bfloat162float(h1));
        __nv_bfloat16 l2 = __float2bfloat16(v.z - __bfloat162float(h2));
        __nv_bfloat16 l3 = __float2bfloat16(v.w - __bfloat162float(h3));
        *(__nv_bfloat162*)&g_AOhi[base]   = __halves2bfloat162(h0, h1);
        *(__nv_bfloat162*)&g_AOhi[base+2] = __halves2bfloat162(h2, h3);
        *(__nv_bfloat162*)&g_AOlo[base]   = __halves2bfloat162(l0, l1);
        *(__nv_bfloat162*)&g_AOlo[base+2] = __halves2bfloat162(l2, l3);
    }
}

// ---------------------------------------------------------------------------

extern "C" void kernel_launch(void* const* d_in, const int* in_sizes, int n_in,
                              void* d_out, int out_size)
{
    const float* X    = (const float*)d_in[0];   // [2,2048,1024]
    const float* Wqkv = (const float*)d_in[1];   // [3072,1024]
    const float* Wout = (const float*)d_in[2];   // [1024,1024]
    float* out = (float*)d_out;                  // [2,2048,1024]

    const int ATTN_SMEM = (64*68*2 + 64*64 + 64*65 + 3*64) * (int)sizeof(float); // 68608 B
    cudaFuncSetAttribute(attn_kernel, cudaFuncAttributeMaxDynamicSharedMemorySize, ATTN_SMEM);
    cudaFuncSetAttribute(gemm_split_kernel, cudaFuncAttributeMaxDynamicSharedMemorySize, GEMM_SMEM);

    split_convert<<<(MT*ND/4)/256,    256>>>(X,    0, MT*ND/4);
    split_convert<<<(QKV_N*ND/4)/256, 256>>>(Wqkv, 1, QKV_N*ND/4);
    split_convert<<<(ND*ND/4)/256,    256>>>(Wout, 2, ND*ND/4);

    gemm_split_kernel<<<dim3(QKV_N/128, MT/128), 256, GEMM_SMEM>>>(nullptr, 1);
    attn_kernel<<<dim3(NS/64, NB*NH), 256, ATTN_SMEM>>>();
    gemm_split_kernel<<<dim3(ND/128, MT/128), 256, GEMM_SMEM>>>(out, 0);
}

// round 7
// speedup vs baseline: 2.2394x; 1.3126x over previous
#include <cuda_runtime.h>
#include <cuda_bf16.h>
#include <math.h>
#include <stdint.h>

#define NS 2048
#define NB 2
#define NH 16
#define NDK 64
#define ND 1024
#define MT (NB*NS)          // 4096 rows total
#define QKV_N (3*ND)        // 3072

// single dynamic-shared symbol for the whole TU (kernels cast as needed)
extern __shared__ char dynsm[];

// Scratch (allocation-free rule: __device__ globals)
__device__ __nv_bfloat16 g_Xhi[MT*ND];
__device__ __nv_bfloat16 g_Xlo[MT*ND];
__device__ __nv_bfloat16 g_Whi[QKV_N*ND];
__device__ __nv_bfloat16 g_Wlo[QKV_N*ND];
__device__ __nv_bfloat16 g_Ohi[ND*ND];
__device__ __nv_bfloat16 g_Olo[ND*ND];
__device__ __nv_bfloat16 g_AOhi[MT*ND];
__device__ __nv_bfloat16 g_AOlo[MT*ND];
__device__ __nv_bfloat16 g_Qhi[NB*NH*NS*NDK];   // [b][h][s][d]
__device__ __nv_bfloat16 g_Qlo[NB*NH*NS*NDK];
__device__ __nv_bfloat16 g_Khi[NB*NH*NS*NDK];
__device__ __nv_bfloat16 g_Klo[NB*NH*NS*NDK];
__device__ __nv_bfloat16 g_Vhi[NB*NH*NS*NDK];
__device__ __nv_bfloat16 g_Vlo[NB*NH*NS*NDK];

// ---------------------------------------------------------------------------
// helpers (portable PTX only: mma.sync / ldmatrix / cp.async — no tcgen05)
// ---------------------------------------------------------------------------
__device__ __forceinline__ uint32_t smem_u32(const void* p){
    uint32_t a;
    asm("{ .reg .u64 t; cvta.to.shared.u64 t, %1; cvt.u32.u64 %0, t; }" : "=r"(a) : "l"(p));
    return a;
}
__device__ __forceinline__ void cp16(uint32_t saddr, const void* g){
    asm volatile("cp.async.cg.shared.global [%0], [%1], 16;" :: "r"(saddr), "l"(g));
}
__device__ __forceinline__ void cp_commit(){
    asm volatile("cp.async.commit_group;" ::: "memory");
}
__device__ __forceinline__ void ldsm_x4(uint32_t r[4], uint32_t addr){
    asm volatile("ldmatrix.sync.aligned.m8n8.x4.shared.b16 {%0,%1,%2,%3}, [%4];"
                 : "=r"(r[0]), "=r"(r[1]), "=r"(r[2]), "=r"(r[3]) : "r"(addr));
}
__device__ __forceinline__ void ldsm_x4_t(uint32_t r[4], uint32_t addr){
    asm volatile("ldmatrix.sync.aligned.m8n8.x4.trans.shared.b16 {%0,%1,%2,%3}, [%4];"
                 : "=r"(r[0]), "=r"(r[1]), "=r"(r[2]), "=r"(r[3]) : "r"(addr));
}
__device__ __forceinline__ void mma_bf16(float c[4], const uint32_t a[4],
                                         const uint32_t b0, const uint32_t b1){
    asm volatile(
        "mma.sync.aligned.m16n8k16.row.col.f32.bf16.bf16.f32 "
        "{%0,%1,%2,%3}, {%4,%5,%6,%7}, {%8,%9}, {%0,%1,%2,%3};"
        : "+f"(c[0]), "+f"(c[1]), "+f"(c[2]), "+f"(c[3])
        : "r"(a[0]), "r"(a[1]), "r"(a[2]), "r"(a[3]), "r"(b0), "r"(b1));
}
__device__ __forceinline__ uint32_t packbf(float a, float b){
    __nv_bfloat162 t = __floats2bfloat162_rn(a, b);
    return *(uint32_t*)&t;
}

// ---------------------------------------------------------------------------
// fp32 -> (bf16 hi, bf16 lo) split. which: 0=X, 1=Wqkv, 2=Wout
// ---------------------------------------------------------------------------
__global__ void __launch_bounds__(256)
split_convert(const float* __restrict__ src, int which, int n4)
{
    int i = blockIdx.x * 256 + threadIdx.x;
    if (i >= n4) return;
    __nv_bfloat16 *hi, *lo;
    if (which == 0)      { hi = g_Xhi; lo = g_Xlo; }
    else if (which == 1) { hi = g_Whi; lo = g_Wlo; }
    else                 { hi = g_Ohi; lo = g_Olo; }
    float4 v = ((const float4*)src)[i];
    __nv_bfloat16 h0 = __float2bfloat16(v.x);
    __nv_bfloat16 h1 = __float2bfloat16(v.y);
    __nv_bfloat16 h2 = __float2bfloat16(v.z);
    __nv_bfloat16 h3 = __float2bfloat16(v.w);
    __nv_bfloat16 l0 = __float2bfloat16(v.x - __bfloat162float(h0));
    __nv_bfloat16 l1 = __float2bfloat16(v.y - __bfloat162float(h1));
    __nv_bfloat16 l2 = __float2bfloat16(v.z - __bfloat162float(h2));
    __nv_bfloat16 l3 = __float2bfloat16(v.w - __bfloat162float(h3));
    ((__nv_bfloat162*)hi)[2*i]   = __halves2bfloat162(h0, h1);
    ((__nv_bfloat162*)hi)[2*i+1] = __halves2bfloat162(h2, h3);
    ((__nv_bfloat162*)lo)[2*i]   = __halves2bfloat162(l0, l1);
    ((__nv_bfloat162*)lo)[2*i+1] = __halves2bfloat162(l2, l3);
}

// ---------------------------------------------------------------------------
// Split-bf16 warp-MMA GEMM: C[m,n] = sum_k A[m,k]*B[n,k], K=1024.
// CTA tile 128x128, 8 warps (2x4), warp tile 64x32, K chunk 64, 2-stage
// cp.async pipeline, XOR-swizzled smem rows for conflict-free ldmatrix.
// mode 1: A=Xhi/lo, B=Wqkv hi/lo -> scatter bf16 hi/lo into g_{Q,K,V}{hi,lo}.
// mode 0: A=AO hi/lo, B=Wout hi/lo -> Cout [MT x ND] fp32.
// ---------------------------------------------------------------------------
#define KC 64
#define ARR_BYTES (128*128)             // 128 rows x 64 bf16 = 16KB
#define STAGE_BYTES (4*ARR_BYTES)       // Ahi, Alo, Bhi, Blo = 64KB
#define GEMM_SMEM (2*STAGE_BYTES)       // 128KB (epilogue reuses it)

__global__ void __launch_bounds__(256, 1)
gemm_split_kernel(float* __restrict__ Cout, int mode)
{
    char* sm = dynsm;
    const int tid = threadIdx.x;
    const int wid = tid >> 5, lane = tid & 31;
    const int m0 = blockIdx.y * 128;
    const int n0 = blockIdx.x * 128;

    const __nv_bfloat16 *Ahi, *Alo, *Bhi, *Blo;
    if (mode == 1) { Ahi = g_Xhi;  Alo = g_Xlo;  Bhi = g_Whi; Blo = g_Wlo; }
    else           { Ahi = g_AOhi; Alo = g_AOlo; Bhi = g_Ohi; Blo = g_Olo; }

    const uint32_t smb = smem_u32(sm);

    const int wm0 = (wid >> 2) * 64;
    const int wn0 = (wid & 3) * 32;

    float acc[4][4][4];
#pragma unroll
    for (int a = 0; a < 4; a++)
#pragma unroll
        for (int b = 0; b < 4; b++)
#pragma unroll
            for (int c = 0; c < 4; c++) acc[a][b][c] = 0.f;

    auto load_stage = [&](int stage, int k0) {
        uint32_t sb = smb + stage * STAGE_BYTES;
        const __nv_bfloat16* srcs[4] = {Ahi, Alo, Bhi, Blo};
#pragma unroll
        for (int arr = 0; arr < 4; arr++) {
            const __nv_bfloat16* src = srcs[arr];
            const int base0 = (arr < 2) ? m0 : n0;
            uint32_t abase = sb + arr * ARR_BYTES;
#pragma unroll
            for (int c = 0; c < 4; c++) {
                int linear = c * 256 + tid;
                int row = linear >> 3;
                int cb  = linear & 7;
                uint32_t sa = abase + row * 128 + ((cb ^ (row & 7)) << 4);
                cp16(sa, src + (size_t)(base0 + row) * ND + k0 + cb * 8);
            }
        }
        cp_commit();
    };

    load_stage(0, 0);

#pragma unroll 1
    for (int i = 0; i < 16; i++) {
        if (i < 15) load_stage((i + 1) & 1, (i + 1) * KC);
        if (i < 15) asm volatile("cp.async.wait_group 1;" ::: "memory");
        else        asm volatile("cp.async.wait_group 0;" ::: "memory");
        __syncthreads();

        uint32_t sb = smb + (i & 1) * STAGE_BYTES;
        uint32_t a_hi_b = sb, a_lo_b = sb + ARR_BYTES;
        uint32_t b_hi_b = sb + 2*ARR_BYTES, b_lo_b = sb + 3*ARR_BYTES;

#pragma unroll
        for (int ks = 0; ks < 4; ks++) {
            uint32_t ah[4][4], al[4][4];
            {
                int row = (lane & 15);
                int kb  = ks * 2 + (lane >> 4);
#pragma unroll
                for (int mt = 0; mt < 4; mt++) {
                    int r = wm0 + mt * 16 + row;
                    uint32_t off = r * 128 + (((uint32_t)(kb ^ (r & 7))) << 4);
                    ldsm_x4(ah[mt], a_hi_b + off);
                    ldsm_x4(al[mt], a_lo_b + off);
                }
            }
            uint32_t bh[4][2], bl[4][2];
            {
                int g = lane >> 3;
                int trow = lane & 7;
#pragma unroll
                for (int p = 0; p < 2; p++) {
                    int nrow = wn0 + (p * 2 + (g >> 1)) * 8 + trow;
                    int kb = ks * 2 + (g & 1);
                    uint32_t off = nrow * 128 + (((uint32_t)(kb ^ (nrow & 7))) << 4);
                    uint32_t r4[4];
                    ldsm_x4(r4, b_hi_b + off);
                    bh[p*2][0] = r4[0]; bh[p*2][1] = r4[1];
                    bh[p*2+1][0] = r4[2]; bh[p*2+1][1] = r4[3];
                    ldsm_x4(r4, b_lo_b + off);
                    bl[p*2][0] = r4[0]; bl[p*2][1] = r4[1];
                    bl[p*2+1][0] = r4[2]; bl[p*2+1][1] = r4[3];
                }
            }
#pragma unroll
            for (int mt = 0; mt < 4; mt++)
#pragma unroll
                for (int nt = 0; nt < 4; nt++) {
                    mma_bf16(acc[mt][nt], ah[mt], bh[nt][0], bh[nt][1]);
                    mma_bf16(acc[mt][nt], ah[mt], bl[nt][0], bl[nt][1]);
                    mma_bf16(acc[mt][nt], al[mt], bh[nt][0], bh[nt][1]);
                }
        }
        __syncthreads();
    }

    // ---- epilogue: acc -> smem (128x132 f32) -> global ----
    float* sf = (float*)sm;
    const int g = lane >> 2, t = lane & 3;
#pragma unroll
    for (int mt = 0; mt < 4; mt++)
#pragma unroll
        for (int nt = 0; nt < 4; nt++) {
            int m = wm0 + mt * 16 + g;
            int n = wn0 + nt * 8 + 2 * t;
            sf[m * 132 + n]       = acc[mt][nt][0];
            sf[m * 132 + n + 1]   = acc[mt][nt][1];
            sf[(m + 8) * 132 + n]     = acc[mt][nt][2];
            sf[(m + 8) * 132 + n + 1] = acc[mt][nt][3];
        }
    __syncthreads();

    const int cgrp = (tid & 7) * 4;
    const int rr0  = tid >> 3;
#pragma unroll 1
    for (int cb = 0; cb < 4; cb++) {
        const int col0 = n0 + cb * 32;
        if (mode == 0) {
#pragma unroll
            for (int it = 0; it < 4; it++) {
                int r = rr0 + it * 32;
                float4 v = *(const float4*)&sf[r * 132 + cb * 32 + cgrp];
                *(float4*)&Cout[(size_t)(m0 + r) * ND + col0 + cgrp] = v;
            }
        } else {
            int part = col0 >> 10;
            int rem  = col0 & 1023;
            int h    = rem >> 6;
            int d0   = (rem & 63) + cgrp;
            __nv_bfloat16 *dhi, *dlo;
            if (part == 0)      { dhi = g_Qhi; dlo = g_Qlo; }
            else if (part == 1) { dhi = g_Khi; dlo = g_Klo; }
            else                { dhi = g_Vhi; dlo = g_Vlo; }
#pragma unroll
            for (int it = 0; it < 4; it++) {
                int r = rr0 + it * 32;
                int m = m0 + r;
                int b = m >> 11, s = m & 2047;
                float4 v = *(const float4*)&sf[r * 132 + cb * 32 + cgrp];
                size_t base = (((size_t)(b * NH + h)) * NS + s) * NDK + d0;
                float h0 = __bfloat162float(__float2bfloat16(v.x));
                float h1 = __bfloat162float(__float2bfloat16(v.y));
                float h2 = __bfloat162float(__float2bfloat16(v.z));
                float h3 = __bfloat162float(__float2bfloat16(v.w));
                *(uint32_t*)&dhi[base]   = packbf(v.x, v.y);
                *(uint32_t*)&dhi[base+2] = packbf(v.z, v.w);
                *(uint32_t*)&dlo[base]   = packbf(v.x - h0, v.y - h1);
                *(uint32_t*)&dlo[base+2] = packbf(v.z - h2, v.w - h3);
            }
        }
    }
}

// ---------------------------------------------------------------------------
// Stage 2: causal flash attention on mma.sync, split-bf16 throughout.
// BQ=128 (8 warps x 16 rows), BK=64, double-buffered K/V via cp.async.
// Q fragments live in registers; softmax fully in accumulator fragments.
// grid = (16 qtiles [reversed], 32 bh)
// ---------------------------------------------------------------------------
#define BQ 128
#define ATTN_SMEM_B (32768 + 2*32768)   // Q hi/lo 32KB + 2 stages x (K/V hi/lo 32KB)

__global__ void __launch_bounds__(256, 1)
attn_mma_kernel()
{
    const uint32_t smb = smem_u32(dynsm);
    const int tid = threadIdx.x;
    const int wid = tid >> 5, lane = tid & 31;
    const int qb = 15 - (int)blockIdx.x;      // biggest q-tiles first
    const int bh = blockIdx.y;
    const int q0 = qb * BQ;
    const int nkt = 2*qb + 2;

    const size_t bho = (size_t)bh * NS * NDK;
    const __nv_bfloat16* Qhg = g_Qhi + bho;
    const __nv_bfloat16* Qlg = g_Qlo + bho;
    const __nv_bfloat16* Khg = g_Khi + bho;
    const __nv_bfloat16* Klg = g_Klo + bho;
    const __nv_bfloat16* Vhg = g_Vhi + bho;
    const __nv_bfloat16* Vlg = g_Vlo + bho;

    // prologue: Q tile (128 x 64 hi/lo) -> smem [row][d] swizzled
#pragma unroll
    for (int c = 0; c < 4; c++) {
        int linear = c*256 + tid;
        int row = linear >> 3, cb = linear & 7;
        uint32_t sa = smb + row*128 + ((cb ^ (row & 7)) << 4);
        cp16(sa,         Qhg + (size_t)(q0 + row)*NDK + cb*8);
        cp16(sa + 16384, Qlg + (size_t)(q0 + row)*NDK + cb*8);
    }
    auto load_stage = [&](int stage, int k0){
        uint32_t sb = smb + 32768 + stage*32768;
        const __nv_bfloat16* srcs[4] = {Khg, Klg, Vhg, Vlg};
#pragma unroll
        for (int arr = 0; arr < 4; arr++) {
#pragma unroll
            for (int c = 0; c < 2; c++) {
                int linear = c*256 + tid;
                int row = linear >> 3, cb = linear & 7;
                uint32_t sa = sb + arr*8192 + row*128 + ((cb ^ (row & 7)) << 4);
                cp16(sa, srcs[arr] + (size_t)(k0 + row)*NDK + cb*8);
            }
        }
        cp_commit();
    };
    load_stage(0, 0);    // Q loads fold into this first group
    asm volatile("cp.async.wait_group 0;" ::: "memory");
    __syncthreads();

    // Q fragments (held in regs for the whole kernel)
    uint32_t qh[4][4], ql[4][4];
    {
        int r = wid*16 + (lane & 15);
#pragma unroll
        for (int ks = 0; ks < 4; ks++) {
            int cb = ks*2 + (lane >> 4);
            uint32_t off = r*128 + (((uint32_t)(cb ^ (r & 7))) << 4);
            ldsm_x4(qh[ks], smb + off);
            ldsm_x4(ql[ks], smb + 16384 + off);
        }
    }

    float o[8][4];
#pragma unroll
    for (int nt = 0; nt < 8; nt++)
#pragma unroll
        for (int f = 0; f < 4; f++) o[nt][f] = 0.f;
    float mrow[2] = {-INFINITY, -INFINITY};
    float lrow[2] = {0.f, 0.f};

#pragma unroll 1
    for (int kt = 0; kt < nkt; kt++) {
        if (kt + 1 < nkt) {
            load_stage((kt + 1) & 1, (kt + 1) * 64);
            asm volatile("cp.async.wait_group 1;" ::: "memory");
        } else {
            asm volatile("cp.async.wait_group 0;" ::: "memory");
        }
        __syncthreads();
        uint32_t sb = smb + 32768 + (kt & 1)*32768;

        // ---- S = Q.K^T (split 3-pass), 16x64 per warp ----
        float s[8][4];
#pragma unroll
        for (int nt = 0; nt < 8; nt++)
#pragma unroll
            for (int f = 0; f < 4; f++) s[nt][f] = 0.f;

#pragma unroll
        for (int ks = 0; ks < 4; ks++) {
#pragma unroll
            for (int half = 0; half < 2; half++) {
                uint32_t kh4[4][2], kl4[4][2];
                int g = lane >> 3, trow = lane & 7;
#pragma unroll
                for (int p = 0; p < 2; p++) {
                    int nrow = half*32 + (p*2 + (g >> 1))*8 + trow;
                    int kb = ks*2 + (g & 1);
                    uint32_t off = nrow*128 + (((uint32_t)(kb ^ (nrow & 7))) << 4);
                    uint32_t r4[4];
                    ldsm_x4(r4, sb + off);
                    kh4[p*2][0] = r4[0]; kh4[p*2][1] = r4[1];
                    kh4[p*2+1][0] = r4[2]; kh4[p*2+1][1] = r4[3];
                    ldsm_x4(r4, sb + 8192 + off);
                    kl4[p*2][0] = r4[0]; kl4[p*2][1] = r4[1];
                    kl4[p*2+1][0] = r4[2]; kl4[p*2+1][1] = r4[3];
                }
#pragma unroll
                for (int nt = 0; nt < 4; nt++) {
                    float* acc = s[half*4 + nt];
                    mma_bf16(acc, qh[ks], kh4[nt][0], kh4[nt][1]);
                    mma_bf16(acc, qh[ks], kl4[nt][0], kl4[nt][1]);
                    mma_bf16(acc, ql[ks], kh4[nt][0], kh4[nt][1]);
                }
            }
        }

        // ---- scale + causal mask ----
#pragma unroll
        for (int nt = 0; nt < 8; nt++)
#pragma unroll
            for (int f = 0; f < 4; f++) s[nt][f] *= 0.125f;
        if (kt >= nkt - 2) {
            int lim0 = q0 + wid*16 + (lane >> 2) - kt*64;   // row r0
#pragma unroll
            for (int nt = 0; nt < 8; nt++) {
                int cb = nt*8 + (lane & 3)*2;
                if (cb     > lim0)     s[nt][0] = -INFINITY;
                if (cb + 1 > lim0)     s[nt][1] = -INFINITY;
                if (cb     > lim0 + 8) s[nt][2] = -INFINITY;
                if (cb + 1 > lim0 + 8) s[nt][3] = -INFINITY;
            }
        }

        // ---- online softmax in fragments; pack P hi/lo ----
        uint32_t phi[8][2], plo[8][2];
#pragma unroll
        for (int rh = 0; rh < 2; rh++) {
            float tm = -INFINITY;
#pragma unroll
            for (int nt = 0; nt < 8; nt++)
                tm = fmaxf(tm, fmaxf(s[nt][2*rh], s[nt][2*rh+1]));
            tm = fmaxf(tm, __shfl_xor_sync(0xffffffffu, tm, 1));
            tm = fmaxf(tm, __shfl_xor_sync(0xffffffffu, tm, 2));
            float mn  = fmaxf(mrow[rh], tm);
            float sc  = __expf(mrow[rh] - mn);
            float sum = 0.f;
#pragma unroll
            for (int nt = 0; nt < 8; nt++) {
                float p0 = __expf(s[nt][2*rh]     - mn);
                float p1 = __expf(s[nt][2*rh + 1] - mn);
                sum += p0 + p1;
                float h0 = __bfloat162float(__float2bfloat16(p0));
                float h1 = __bfloat162float(__float2bfloat16(p1));
                phi[nt][rh] = packbf(p0, p1);
                plo[nt][rh] = packbf(p0 - h0, p1 - h1);
            }
            sum += __shfl_xor_sync(0xffffffffu, sum, 1);
            sum += __shfl_xor_sync(0xffffffffu, sum, 2);
            lrow[rh] = lrow[rh]*sc + sum;
            mrow[rh] = mn;
#pragma unroll
            for (int nt = 0; nt < 8; nt++) {
                o[nt][2*rh]     *= sc;
                o[nt][2*rh + 1] *= sc;
            }
        }

        // ---- O += P.V (split 3-pass), V via ldmatrix.trans on [key][d] ----
#pragma unroll
        for (int ks = 0; ks < 4; ks++) {
            uint32_t aph[4] = {phi[2*ks][0], phi[2*ks][1], phi[2*ks+1][0], phi[2*ks+1][1]};
            uint32_t apl[4] = {plo[2*ks][0], plo[2*ks][1], plo[2*ks+1][0], plo[2*ks+1][1]};
#pragma unroll
            for (int dh = 0; dh < 4; dh++) {
                int r  = 16*ks + (lane & 15);
                int cb = dh*2 + (lane >> 4);
                uint32_t off = r*128 + (((uint32_t)(cb ^ (r & 7))) << 4);
                uint32_t vh[4], vl[4];
                ldsm_x4_t(vh, sb + 16384 + off);
                ldsm_x4_t(vl, sb + 24576 + off);
                mma_bf16(o[dh*2],   aph, vh[0], vh[1]);
                mma_bf16(o[dh*2],   aph, vl[0], vl[1]);
                mma_bf16(o[dh*2],   apl, vh[0], vh[1]);
                mma_bf16(o[dh*2+1], aph, vh[2], vh[3]);
                mma_bf16(o[dh*2+1], aph, vl[2], vl[3]);
                mma_bf16(o[dh*2+1], apl, vh[2], vh[3]);
            }
        }
        __syncthreads();
    }

    // ---- epilogue: O / l -> split bf16 hi/lo at [b*s][h*dk] ----
    const int b = bh >> 4, h = bh & 15;
#pragma unroll
    for (int rh = 0; rh < 2; rh++) {
        float inv = 1.0f / lrow[rh];
        int qrow = q0 + wid*16 + (lane >> 2) + rh*8;
        size_t rowbase = ((size_t)(b*NS + qrow))*ND + h*NDK;
#pragma unroll
        for (int nt = 0; nt < 8; nt++) {
            float v0 = o[nt][2*rh]     * inv;
            float v1 = o[nt][2*rh + 1] * inv;
            size_t idx = rowbase + nt*8 + (lane & 3)*2;
            float h0 = __bfloat162float(__float2bfloat16(v0));
            float h1 = __bfloat162float(__float2bfloat16(v1));
            *(uint32_t*)&g_AOhi[idx] = packbf(v0, v1);
            *(uint32_t*)&g_AOlo[idx] = packbf(v0 - h0, v1 - h1);
        }
    }
}

// ---------------------------------------------------------------------------

extern "C" void kernel_launch(void* const* d_in, const int* in_sizes, int n_in,
                              void* d_out, int out_size)
{
    const float* X    = (const float*)d_in[0];   // [2,2048,1024]
    const float* Wqkv = (const float*)d_in[1];   // [3072,1024]
    const float* Wout = (const float*)d_in[2];   // [1024,1024]
    float* out = (float*)d_out;                  // [2,2048,1024]

    cudaFuncSetAttribute(gemm_split_kernel, cudaFuncAttributeMaxDynamicSharedMemorySize, GEMM_SMEM);
    cudaFuncSetAttribute(attn_mma_kernel,  cudaFuncAttributeMaxDynamicSharedMemorySize, ATTN_SMEM_B);

    split_convert<<<(MT*ND/4)/256,    256>>>(X,    0, MT*ND/4);
    split_convert<<<(QKV_N*ND/4)/256, 256>>>(Wqkv, 1, QKV_N*ND/4);
    split_convert<<<(ND*ND/4)/256,    256>>>(Wout, 2, ND*ND/4);

    gemm_split_kernel<<<dim3(QKV_N/128, MT/128), 256, GEMM_SMEM>>>(nullptr, 1);
    attn_mma_kernel<<<dim3(NS/BQ, NB*NH), 256, ATTN_SMEM_B>>>();
    gemm_split_kernel<<<dim3(ND/128, MT/128), 256, GEMM_SMEM>>>(out, 0);
}

// round 8
// speedup vs baseline: 3.5075x; 1.5663x over previous
#include <cuda_runtime.h>
#include <cuda_bf16.h>
#include <math.h>
#include <stdint.h>

#define NS 2048
#define NB 2
#define NH 16
#define NDK 64
#define ND 1024
#define MT (NB*NS)          // 4096 rows total
#define QKV_N (3*ND)        // 3072

// single dynamic-shared symbol for the whole TU (kernels cast as needed)
extern __shared__ char dynsm[];

// Scratch (allocation-free rule: __device__ globals)
__device__ __nv_bfloat16 g_Xhi[MT*ND];
__device__ __nv_bfloat16 g_Xlo[MT*ND];
__device__ __nv_bfloat16 g_Whi[QKV_N*ND];
__device__ __nv_bfloat16 g_Wlo[QKV_N*ND];
__device__ __nv_bfloat16 g_Ohi[ND*ND];
__device__ __nv_bfloat16 g_Olo[ND*ND];
__device__ __nv_bfloat16 g_AOhi[MT*ND];
__device__ __nv_bfloat16 g_AOlo[MT*ND];
__device__ __nv_bfloat16 g_Qhi[NB*NH*NS*NDK];   // [b][h][s][d]
__device__ __nv_bfloat16 g_Qlo[NB*NH*NS*NDK];
__device__ __nv_bfloat16 g_Khi[NB*NH*NS*NDK];
__device__ __nv_bfloat16 g_Klo[NB*NH*NS*NDK];
__device__ __nv_bfloat16 g_Vhi[NB*NH*NS*NDK];
__device__ __nv_bfloat16 g_Vlo[NB*NH*NS*NDK];

// ---------------------------------------------------------------------------
// helpers (portable PTX only: mma.sync / ldmatrix / cp.async — no tcgen05)
// ---------------------------------------------------------------------------
__device__ __forceinline__ uint32_t smem_u32(const void* p){
    uint32_t a;
    asm("{ .reg .u64 t; cvta.to.shared.u64 t, %1; cvt.u32.u64 %0, t; }" : "=r"(a) : "l"(p));
    return a;
}
__device__ __forceinline__ void cp16(uint32_t saddr, const void* g){
    asm volatile("cp.async.cg.shared.global [%0], [%1], 16;" :: "r"(saddr), "l"(g));
}
__device__ __forceinline__ void cp_commit(){
    asm volatile("cp.async.commit_group;" ::: "memory");
}
__device__ __forceinline__ void ldsm_x4(uint32_t r[4], uint32_t addr){
    asm volatile("ldmatrix.sync.aligned.m8n8.x4.shared.b16 {%0,%1,%2,%3}, [%4];"
                 : "=r"(r[0]), "=r"(r[1]), "=r"(r[2]), "=r"(r[3]) : "r"(addr));
}
__device__ __forceinline__ void ldsm_x4_t(uint32_t r[4], uint32_t addr){
    asm volatile("ldmatrix.sync.aligned.m8n8.x4.trans.shared.b16 {%0,%1,%2,%3}, [%4];"
                 : "=r"(r[0]), "=r"(r[1]), "=r"(r[2]), "=r"(r[3]) : "r"(addr));
}
__device__ __forceinline__ void mma_bf16(float c[4], const uint32_t a[4],
                                         const uint32_t b0, const uint32_t b1){
    asm volatile(
        "mma.sync.aligned.m16n8k16.row.col.f32.bf16.bf16.f32 "
        "{%0,%1,%2,%3}, {%4,%5,%6,%7}, {%8,%9}, {%0,%1,%2,%3};"
        : "+f"(c[0]), "+f"(c[1]), "+f"(c[2]), "+f"(c[3])
        : "r"(a[0]), "r"(a[1]), "r"(a[2]), "r"(a[3]), "r"(b0), "r"(b1));
}
__device__ __forceinline__ uint32_t packbf(float a, float b){
    __nv_bfloat162 t = __floats2bfloat162_rn(a, b);
    return *(uint32_t*)&t;
}

// ---------------------------------------------------------------------------
// fp32 -> (bf16 hi, bf16 lo) split. which: 0=X, 1=Wqkv, 2=Wout
// ---------------------------------------------------------------------------
__global__ void __launch_bounds__(256)
split_convert(const float* __restrict__ src, int which, int n4)
{
    int i = blockIdx.x * 256 + threadIdx.x;
    if (i >= n4) return;
    __nv_bfloat16 *hi, *lo;
    if (which == 0)      { hi = g_Xhi; lo = g_Xlo; }
    else if (which == 1) { hi = g_Whi; lo = g_Wlo; }
    else                 { hi = g_Ohi; lo = g_Olo; }
    float4 v = ((const float4*)src)[i];
    __nv_bfloat16 h0 = __float2bfloat16(v.x);
    __nv_bfloat16 h1 = __float2bfloat16(v.y);
    __nv_bfloat16 h2 = __float2bfloat16(v.z);
    __nv_bfloat16 h3 = __float2bfloat16(v.w);
    __nv_bfloat16 l0 = __float2bfloat16(v.x - __bfloat162float(h0));
    __nv_bfloat16 l1 = __float2bfloat16(v.y - __bfloat162float(h1));
    __nv_bfloat16 l2 = __float2bfloat16(v.z - __bfloat162float(h2));
    __nv_bfloat16 l3 = __float2bfloat16(v.w - __bfloat162float(h3));
    ((__nv_bfloat162*)hi)[2*i]   = __halves2bfloat162(h0, h1);
    ((__nv_bfloat162*)hi)[2*i+1] = __halves2bfloat162(h2, h3);
    ((__nv_bfloat162*)lo)[2*i]   = __halves2bfloat162(l0, l1);
    ((__nv_bfloat162*)lo)[2*i+1] = __halves2bfloat162(l2, l3);
}

// ---------------------------------------------------------------------------
// Split-bf16 warp-MMA GEMM: C[m,n] = sum_k A[m,k]*B[n,k], K=1024.
// CTA tile 256x128, 8 warps (4m x 2n), warp tile 64x64, K chunk 64,
// 2-stage cp.async pipeline, XOR-swizzled rows, 3 passes (hh, hl, lh).
// mode 1: A=Xhi/lo, B=Wqkv hi/lo -> scatter bf16 hi/lo into g_{Q,K,V}{hi,lo}.
// mode 0: A=AO hi/lo, B=Wout hi/lo -> Cout [MT x ND] fp32.
// ---------------------------------------------------------------------------
#define KC 64
#define A_ARR (256*128)                 // 256 rows x 128B = 32KB
#define B_ARR (128*128)                 // 128 rows x 128B = 16KB
#define STAGE_BYTES (2*A_ARR + 2*B_ARR) // 96KB
#define GEMM_SMEM (2*STAGE_BYTES)       // 192KB (epilogue reuses it)

__global__ void __launch_bounds__(256, 1)
gemm_split_kernel(float* __restrict__ Cout, int mode)
{
    char* sm = dynsm;
    const int tid = threadIdx.x;
    const int wid = tid >> 5, lane = tid & 31;
    const int m0 = blockIdx.y * 256;
    const int n0 = blockIdx.x * 128;

    const __nv_bfloat16 *Ahi, *Alo, *Bhi, *Blo;
    if (mode == 1) { Ahi = g_Xhi;  Alo = g_Xlo;  Bhi = g_Whi; Blo = g_Wlo; }
    else           { Ahi = g_AOhi; Alo = g_AOlo; Bhi = g_Ohi; Blo = g_Olo; }

    const uint32_t smb = smem_u32(sm);

    // warp layout: 4 (m) x 2 (n); warp tile 64x64
    const int wm0 = (wid >> 1) * 64;
    const int wn0 = (wid & 1) * 64;

    float acc[4][8][4];
#pragma unroll
    for (int a = 0; a < 4; a++)
#pragma unroll
        for (int b = 0; b < 8; b++)
#pragma unroll
            for (int c = 0; c < 4; c++) acc[a][b][c] = 0.f;

    // ---- global -> smem stage loader (cp.async, 24 x 16B per thread) ----
    auto load_stage = [&](int stage, int k0) {
        uint32_t sb = smb + stage * STAGE_BYTES;
        // A hi/lo: 256 rows each
#pragma unroll
        for (int c = 0; c < 8; c++) {
            int linear = c * 256 + tid;      // 0..2047
            int row = linear >> 3;           // 0..255
            int cb  = linear & 7;
            uint32_t off = row * 128 + ((cb ^ (row & 7)) << 4);
            const size_t g = (size_t)(m0 + row) * ND + k0 + cb * 8;
            cp16(sb + off,         Ahi + g);
            cp16(sb + A_ARR + off, Alo + g);
        }
        // B hi/lo: 128 rows each
#pragma unroll
        for (int c = 0; c < 4; c++) {
            int linear = c * 256 + tid;      // 0..1023
            int row = linear >> 3;           // 0..127
            int cb  = linear & 7;
            uint32_t off = row * 128 + ((cb ^ (row & 7)) << 4);
            const size_t g = (size_t)(n0 + row) * ND + k0 + cb * 8;
            cp16(sb + 2*A_ARR + off,         Bhi + g);
            cp16(sb + 2*A_ARR + B_ARR + off, Blo + g);
        }
        cp_commit();
    };

    load_stage(0, 0);

#pragma unroll 1
    for (int i = 0; i < 16; i++) {
        if (i < 15) load_stage((i + 1) & 1, (i + 1) * KC);
        if (i < 15) asm volatile("cp.async.wait_group 1;" ::: "memory");
        else        asm volatile("cp.async.wait_group 0;" ::: "memory");
        __syncthreads();

        uint32_t sb = smb + (i & 1) * STAGE_BYTES;
        uint32_t a_hi_b = sb, a_lo_b = sb + A_ARR;
        uint32_t b_hi_b = sb + 2*A_ARR, b_lo_b = sb + 2*A_ARR + B_ARR;

#pragma unroll
        for (int ks = 0; ks < 4; ks++) {
            // A fragments: 4 m16 tiles, hi+lo
            uint32_t ah[4][4], al[4][4];
            {
                int row = (lane & 15);
                int kb  = ks * 2 + (lane >> 4);
#pragma unroll
                for (int mt = 0; mt < 4; mt++) {
                    int r = wm0 + mt * 16 + row;
                    uint32_t off = r * 128 + (((uint32_t)(kb ^ (r & 7))) << 4);
                    ldsm_x4(ah[mt], a_hi_b + off);
                    ldsm_x4(al[mt], a_lo_b + off);
                }
            }
            // B in 4 chunks of 2 n8-tiles (keeps frag regs bounded)
            int g = lane >> 3, trow = lane & 7;
#pragma unroll
            for (int p = 0; p < 4; p++) {
                int nrow = wn0 + (p * 2 + (g >> 1)) * 8 + trow;
                int kb = ks * 2 + (g & 1);
                uint32_t off = nrow * 128 + (((uint32_t)(kb ^ (nrow & 7))) << 4);
                uint32_t bh[4], bl[4];
                ldsm_x4(bh, b_hi_b + off);
                ldsm_x4(bl, b_lo_b + off);
#pragma unroll
                for (int mt = 0; mt < 4; mt++) {
                    float* a0 = acc[mt][p*2];
                    float* a1 = acc[mt][p*2+1];
                    mma_bf16(a0, ah[mt], bh[0], bh[1]);
                    mma_bf16(a0, ah[mt], bl[0], bl[1]);
                    mma_bf16(a0, al[mt], bh[0], bh[1]);
                    mma_bf16(a1, ah[mt], bh[2], bh[3]);
                    mma_bf16(a1, ah[mt], bl[2], bl[3]);
                    mma_bf16(a1, al[mt], bh[2], bh[3]);
                }
            }
        }
        __syncthreads();
    }

    // ---- epilogue: acc -> smem (256x132 f32) -> vectorized global ----
    float* sf = (float*)sm;
    const int gq = lane >> 2, tq = lane & 3;
#pragma unroll
    for (int mt = 0; mt < 4; mt++)
#pragma unroll
        for (int nt = 0; nt < 8; nt++) {
            int m = wm0 + mt * 16 + gq;
            int n = wn0 + nt * 8 + 2 * tq;
            sf[m * 132 + n]           = acc[mt][nt][0];
            sf[m * 132 + n + 1]       = acc[mt][nt][1];
            sf[(m + 8) * 132 + n]     = acc[mt][nt][2];
            sf[(m + 8) * 132 + n + 1] = acc[mt][nt][3];
        }
    __syncthreads();

    // each thread: 16 consecutive cols of one row per pass, 8 passes
    const int rr  = tid >> 3;          // 0..31
    const int colg = (tid & 7) * 16;   // 0,16,...,112
#pragma unroll 1
    for (int pass = 0; pass < 8; pass++) {
        int r = pass * 32 + rr;
        const float* src = &sf[r * 132 + colg];
        if (mode == 0) {
            float4* dst = (float4*)&Cout[(size_t)(m0 + r) * ND + n0 + colg];
#pragma unroll
            for (int j = 0; j < 4; j++) dst[j] = ((const float4*)src)[j];
        } else {
            int col0 = n0 + colg;
            int part = col0 >> 10;
            int rem  = col0 & 1023;
            int h    = rem >> 6;
            int d0   = rem & 63;
            __nv_bfloat16 *dhi, *dlo;
            if (part == 0)      { dhi = g_Qhi; dlo = g_Qlo; }
            else if (part == 1) { dhi = g_Khi; dlo = g_Klo; }
            else                { dhi = g_Vhi; dlo = g_Vlo; }
            int m = m0 + r;
            int b = m >> 11, s = m & 2047;
            size_t base = (((size_t)(b * NH + h)) * NS + s) * NDK + d0;
            uint32_t hp[8], lp[8];
#pragma unroll
            for (int j = 0; j < 8; j++) {
                float v0 = src[2*j], v1 = src[2*j+1];
                float h0 = __bfloat162float(__float2bfloat16(v0));
                float h1 = __bfloat162float(__float2bfloat16(v1));
                hp[j] = packbf(v0, v1);
                lp[j] = packbf(v0 - h0, v1 - h1);
            }
            ((uint4*)&dhi[base])[0] = make_uint4(hp[0], hp[1], hp[2], hp[3]);
            ((uint4*)&dhi[base])[1] = make_uint4(hp[4], hp[5], hp[6], hp[7]);
            ((uint4*)&dlo[base])[0] = make_uint4(lp[0], lp[1], lp[2], lp[3]);
            ((uint4*)&dlo[base])[1] = make_uint4(lp[4], lp[5], lp[6], lp[7]);
        }
    }
}

// ---------------------------------------------------------------------------
// Stage 2: causal flash attention on mma.sync, split-bf16 throughout.
// BQ=128 (8 warps x 16 rows), BK=64, double-buffered K/V via cp.async.
// grid = (16 qtiles [reversed], 32 bh)
// ---------------------------------------------------------------------------
#define BQ 128
#define ATTN_SMEM_B (32768 + 2*32768)   // Q hi/lo 32KB + 2 stages x (K/V hi/lo 32KB)

__global__ void __launch_bounds__(256, 1)
attn_mma_kernel()
{
    const uint32_t smb = smem_u32(dynsm);
    const int tid = threadIdx.x;
    const int wid = tid >> 5, lane = tid & 31;
    const int qb = 15 - (int)blockIdx.x;      // biggest q-tiles first
    const int bh = blockIdx.y;
    const int q0 = qb * BQ;
    const int nkt = 2*qb + 2;

    const size_t bho = (size_t)bh * NS * NDK;
    const __nv_bfloat16* Qhg = g_Qhi + bho;
    const __nv_bfloat16* Qlg = g_Qlo + bho;
    const __nv_bfloat16* Khg = g_Khi + bho;
    const __nv_bfloat16* Klg = g_Klo + bho;
    const __nv_bfloat16* Vhg = g_Vhi + bho;
    const __nv_bfloat16* Vlg = g_Vlo + bho;

    // prologue: Q tile (128 x 64 hi/lo) -> smem [row][d] swizzled
#pragma unroll
    for (int c = 0; c < 4; c++) {
        int linear = c*256 + tid;
        int row = linear >> 3, cb = linear & 7;
        uint32_t sa = smb + row*128 + ((cb ^ (row & 7)) << 4);
        cp16(sa,         Qhg + (size_t)(q0 + row)*NDK + cb*8);
        cp16(sa + 16384, Qlg + (size_t)(q0 + row)*NDK + cb*8);
    }
    auto load_stage = [&](int stage, int k0){
        uint32_t sb = smb + 32768 + stage*32768;
        const __nv_bfloat16* srcs[4] = {Khg, Klg, Vhg, Vlg};
#pragma unroll
        for (int arr = 0; arr < 4; arr++) {
#pragma unroll
            for (int c = 0; c < 2; c++) {
                int linear = c*256 + tid;
                int row = linear >> 3, cb = linear & 7;
                uint32_t sa = sb + arr*8192 + row*128 + ((cb ^ (row & 7)) << 4);
                cp16(sa, srcs[arr] + (size_t)(k0 + row)*NDK + cb*8);
            }
        }
        cp_commit();
    };
    load_stage(0, 0);
    asm volatile("cp.async.wait_group 0;" ::: "memory");
    __syncthreads();

    uint32_t qh[4][4], ql[4][4];
    {
        int r = wid*16 + (lane & 15);
#pragma unroll
        for (int ks = 0; ks < 4; ks++) {
            int cb = ks*2 + (lane >> 4);
            uint32_t off = r*128 + (((uint32_t)(cb ^ (r & 7))) << 4);
            ldsm_x4(qh[ks], smb + off);
            ldsm_x4(ql[ks], smb + 16384 + off);
        }
    }

    float o[8][4];
#pragma unroll
    for (int nt = 0; nt < 8; nt++)
#pragma unroll
        for (int f = 0; f < 4; f++) o[nt][f] = 0.f;
    float mrow[2] = {-INFINITY, -INFINITY};
    float lrow[2] = {0.f, 0.f};

#pragma unroll 1
    for (int kt = 0; kt < nkt; kt++) {
        if (kt + 1 < nkt) {
            load_stage((kt + 1) & 1, (kt + 1) * 64);
            asm volatile("cp.async.wait_group 1;" ::: "memory");
        } else {
            asm volatile("cp.async.wait_group 0;" ::: "memory");
        }
        __syncthreads();
        uint32_t sb = smb + 32768 + (kt & 1)*32768;

        // ---- S = Q.K^T (split 3-pass), 16x64 per warp ----
        float s[8][4];
#pragma unroll
        for (int nt = 0; nt < 8; nt++)
#pragma unroll
            for (int f = 0; f < 4; f++) s[nt][f] = 0.f;

#pragma unroll
        for (int ks = 0; ks < 4; ks++) {
#pragma unroll
            for (int half = 0; half < 2; half++) {
                uint32_t kh4[4][2], kl4[4][2];
                int g = lane >> 3, trow = lane & 7;
#pragma unroll
                for (int p = 0; p < 2; p++) {
                    int nrow = half*32 + (p*2 + (g >> 1))*8 + trow;
                    int kb = ks*2 + (g & 1);
                    uint32_t off = nrow*128 + (((uint32_t)(kb ^ (nrow & 7))) << 4);
                    uint32_t r4[4];
                    ldsm_x4(r4, sb + off);
                    kh4[p*2][0] = r4[0]; kh4[p*2][1] = r4[1];
                    kh4[p*2+1][0] = r4[2]; kh4[p*2+1][1] = r4[3];
                    ldsm_x4(r4, sb + 8192 + off);
                    kl4[p*2][0] = r4[0]; kl4[p*2][1] = r4[1];
                    kl4[p*2+1][0] = r4[2]; kl4[p*2+1][1] = r4[3];
                }
#pragma unroll
                for (int nt = 0; nt < 4; nt++) {
                    float* acc = s[half*4 + nt];
                    mma_bf16(acc, qh[ks], kh4[nt][0], kh4[nt][1]);
                    mma_bf16(acc, qh[ks], kl4[nt][0], kl4[nt][1]);
                    mma_bf16(acc, ql[ks], kh4[nt][0], kh4[nt][1]);
                }
            }
        }

        // ---- scale + causal mask ----
#pragma unroll
        for (int nt = 0; nt < 8; nt++)
#pragma unroll
            for (int f = 0; f < 4; f++) s[nt][f] *= 0.125f;
        if (kt >= nkt - 2) {
            int lim0 = q0 + wid*16 + (lane >> 2) - kt*64;
#pragma unroll
            for (int nt = 0; nt < 8; nt++) {
                int cb = nt*8 + (lane & 3)*2;
                if (cb     > lim0)     s[nt][0] = -INFINITY;
                if (cb + 1 > lim0)     s[nt][1] = -INFINITY;
                if (cb     > lim0 + 8) s[nt][2] = -INFINITY;
                if (cb + 1 > lim0 + 8) s[nt][3] = -INFINITY;
            }
        }

        // ---- online softmax in fragments; pack P hi/lo ----
        uint32_t phi[8][2], plo[8][2];
#pragma unroll
        for (int rh = 0; rh < 2; rh++) {
            float tm = -INFINITY;
#pragma unroll
            for (int nt = 0; nt < 8; nt++)
                tm = fmaxf(tm, fmaxf(s[nt][2*rh], s[nt][2*rh+1]));
            tm = fmaxf(tm, __shfl_xor_sync(0xffffffffu, tm, 1));
            tm = fmaxf(tm, __shfl_xor_sync(0xffffffffu, tm, 2));
            float mn  = fmaxf(mrow[rh], tm);
            float sc  = __expf(mrow[rh] - mn);
            float sum = 0.f;
#pragma unroll
            for (int nt = 0; nt < 8; nt++) {
                float p0 = __expf(s[nt][2*rh]     - mn);
                float p1 = __expf(s[nt][2*rh + 1] - mn);
                sum += p0 + p1;
                float h0 = __bfloat162float(__float2bfloat16(p0));
                float h1 = __bfloat162float(__float2bfloat16(p1));
                phi[nt][rh] = packbf(p0, p1);
                plo[nt][rh] = packbf(p0 - h0, p1 - h1);
            }
            sum += __shfl_xor_sync(0xffffffffu, sum, 1);
            sum += __shfl_xor_sync(0xffffffffu, sum, 2);
            lrow[rh] = lrow[rh]*sc + sum;
            mrow[rh] = mn;
#pragma unroll
            for (int nt = 0; nt < 8; nt++) {
                o[nt][2*rh]     *= sc;
                o[nt][2*rh + 1] *= sc;
            }
        }

        // ---- O += P.V (split 3-pass), V via ldmatrix.trans on [key][d] ----
#pragma unroll
        for (int ks = 0; ks < 4; ks++) {
            uint32_t aph[4] = {phi[2*ks][0], phi[2*ks][1], phi[2*ks+1][0], phi[2*ks+1][1]};
            uint32_t apl[4] = {plo[2*ks][0], plo[2*ks][1], plo[2*ks+1][0], plo[2*ks+1][1]};
#pragma unroll
            for (int dh = 0; dh < 4; dh++) {
                int r  = 16*ks + (lane & 15);
                int cb = dh*2 + (lane >> 4);
                uint32_t off = r*128 + (((uint32_t)(cb ^ (r & 7))) << 4);
                uint32_t vh[4], vl[4];
                ldsm_x4_t(vh, sb + 16384 + off);
                ldsm_x4_t(vl, sb + 24576 + off);
                mma_bf16(o[dh*2],   aph, vh[0], vh[1]);
                mma_bf16(o[dh*2],   aph, vl[0], vl[1]);
                mma_bf16(o[dh*2],   apl, vh[0], vh[1]);
                mma_bf16(o[dh*2+1], aph, vh[2], vh[3]);
                mma_bf16(o[dh*2+1], aph, vl[2], vl[3]);
                mma_bf16(o[dh*2+1], apl, vh[2], vh[3]);
            }
        }
        __syncthreads();
    }

    // ---- epilogue: O / l -> split bf16 hi/lo at [b*s][h*dk] ----
    const int b = bh >> 4, h = bh & 15;
#pragma unroll
    for (int rh = 0; rh < 2; rh++) {
        float inv = 1.0f / lrow[rh];
        int qrow = q0 + wid*16 + (lane >> 2) + rh*8;
        size_t rowbase = ((size_t)(b*NS + qrow))*ND + h*NDK;
#pragma unroll
        for (int nt = 0; nt < 8; nt++) {
            float v0 = o[nt][2*rh]     * inv;
            float v1 = o[nt][2*rh + 1] * inv;
            size_t idx = rowbase + nt*8 + (lane & 3)*2;
            float h0 = __bfloat162float(__float2bfloat16(v0));
            float h1 = __bfloat162float(__float2bfloat16(v1));
            *(uint32_t*)&g_AOhi[idx] = packbf(v0, v1);
            *(uint32_t*)&g_AOlo[idx] = packbf(v0 - h0, v1 - h1);
        }
    }
}

// ---------------------------------------------------------------------------

extern "C" void kernel_launch(void* const* d_in, const int* in_sizes, int n_in,
                              void* d_out, int out_size)
{
    const float* X    = (const float*)d_in[0];   // [2,2048,1024]
    const float* Wqkv = (const float*)d_in[1];   // [3072,1024]
    const float* Wout = (const float*)d_in[2];   // [1024,1024]
    float* out = (float*)d_out;                  // [2,2048,1024]

    cudaFuncSetAttribute(gemm_split_kernel, cudaFuncAttributeMaxDynamicSharedMemorySize, GEMM_SMEM);
    cudaFuncSetAttribute(attn_mma_kernel,  cudaFuncAttributeMaxDynamicSharedMemorySize, ATTN_SMEM_B);

    split_convert<<<(MT*ND/4)/256,    256>>>(X,    0, MT*ND/4);
    split_convert<<<(QKV_N*ND/4)/256, 256>>>(Wqkv, 1, QKV_N*ND/4);
    split_convert<<<(ND*ND/4)/256,    256>>>(Wout, 2, ND*ND/4);

    gemm_split_kernel<<<dim3(QKV_N/128, MT/256), 256, GEMM_SMEM>>>(nullptr, 1);
    attn_mma_kernel<<<dim3(NS/BQ, NB*NH), 256, ATTN_SMEM_B>>>();
    gemm_split_kernel<<<dim3(ND/128, MT/256), 256, GEMM_SMEM>>>(out, 0);
}